// round 5
// baseline (speedup 1.0000x reference)
#include <cuda_runtime.h>

// ---------------- problem constants ----------------
#define Bn 16
#define An 3
#define Cn 80
#define Hn 76
#define Wn 76
#define Tn 50
#define HW (Hn * Wn)          // 5776
#define AHW (An * HW)         // 17328
#define NCELL (Bn * An * HW)  // 277248
#define NT (Bn * Tn)          // 800
#define CH (5 + Cn)           // 85
#define NCH (An * CH)         // 255

// ---------------- device scratch (static: no allocations) ----------------
__device__ int    g_win[NCELL];        // winner tag per cell (self-cleaned per launch)
__device__ int    g_nlist, g_npair, g_nzero;
__device__ int    g_mcell[NT];
__device__ float4 g_mt[NT];            // tx, ty, tw, th (winner's values)
__device__ int    g_pair[NT];          // cell*Cn + cls
__device__ int    g_zcell[NT * An];    // noobj-zeroed cells (dupes allowed, negligible)
__device__ double g_acc[8];            // 0:x 1:y 2:w 3:h 4:conf_obj 5:conf_all 6:conf_zero 7:cls

__device__ __forceinline__ float sigf(float v) { return 1.0f / (1.0f + expf(-v)); }
__device__ __forceinline__ float clog(float v) { return fmaxf(logf(v), -100.0f); }

// ---------------- K1: build targets (one block, one thread per (b,t)) ----------------
__global__ void k_targets(const float* __restrict__ tgt)
{
    int tid = threadIdx.x;              // 0..799
    int b = tid / Tn;
    int t = tid - b * Tn;

    const float* p = tgt + tid * 5;
    float c  = p[0], xx = p[1], yy = p[2], ww = p[3], hh = p[4];
    bool valid = (c + xx + yy + ww + hh) != 0.0f;

    float gx = xx * (float)Wn, gy = yy * (float)Hn;
    float gw = ww * (float)Wn, gh = hh * (float)Hn;
    int gi = (int)gx, gj = (int)gy;

    // SA anchors (exact binary constants)
    const float aw0 = 1.25f,  aw1 = 2.0f,  aw2 = 4.125f;
    const float ah0 = 1.625f, ah1 = 3.75f, ah2 = 2.875f;
    const float a20 = 5.90625f, a21 = 14.25f, a22 = 19.859375f; // (aw+1)*(ah+1)

    float a1 = (gw + 1.0f) * (gh + 1.0f);
    float i0 = fmaxf(fminf(gw, aw0) + 1.0f, 0.0f) * fmaxf(fminf(gh, ah0) + 1.0f, 0.0f);
    float i1 = fmaxf(fminf(gw, aw1) + 1.0f, 0.0f) * fmaxf(fminf(gh, ah1) + 1.0f, 0.0f);
    float i2 = fmaxf(fminf(gw, aw2) + 1.0f, 0.0f) * fmaxf(fminf(gh, ah2) + 1.0f, 0.0f);
    float u0 = i0 / (a1 + a20 - i0 + 1e-16f);
    float u1 = i1 / (a1 + a21 - i1 + 1e-16f);
    float u2 = i2 / (a1 + a22 - i2 + 1e-16f);

    int best = 0; float bi = u0;
    if (u1 > bi) { best = 1; bi = u1; }
    if (u2 > bi) { best = 2; bi = u2; }

    bool ok = valid && (gj < Hn) && (gi < Wn) && (gj >= 0) && (gi >= 0);
    int cell = ((b * An + best) * Hn + gj) * Wn + gi;

    // pass 0: per-launch state reset (only touched entries matter)
    if (tid == 0) { g_nlist = 0; g_npair = 0; g_nzero = 0; }
    if (tid < 8)  g_acc[tid] = 0.0;
    if (ok)       g_win[cell] = 0;
    __syncthreads();

    // pass A: winner election + list appends
    if (ok) atomicMax(&g_win[cell], t + 1);

    if (valid) {
        if (u0 > 0.5f) { int z = ((b * An + 0) * Hn + gj) * Wn + gi;
                         if (z >= 0 && z < NCELL) g_zcell[atomicAdd(&g_nzero, 1)] = z; }
        if (u1 > 0.5f) { int z = ((b * An + 1) * Hn + gj) * Wn + gi;
                         if (z >= 0 && z < NCELL) g_zcell[atomicAdd(&g_nzero, 1)] = z; }
        if (u2 > 0.5f) { int z = ((b * An + 2) * Hn + gj) * Wn + gi;
                         if (z >= 0 && z < NCELL) g_zcell[atomicAdd(&g_nzero, 1)] = z; }
    }
    if (ok) g_pair[atomicAdd(&g_npair, 1)] = cell * Cn + (int)c;

    __syncthreads();

    // pass B: winners emit the final (last-wins) target values
    if (ok && g_win[cell] == t + 1) {
        float tx = gx - (float)gi;
        float ty = gy - (float)gj;
        float awb = (best == 0) ? aw0 : (best == 1 ? aw1 : aw2);
        float ahb = (best == 0) ? ah0 : (best == 1 ? ah1 : ah2);
        float tw = logf(gw / awb + 1e-16f);
        float th = logf(gh / ahb + 1e-16f);
        int m = atomicAdd(&g_nlist, 1);
        g_mcell[m] = cell;
        g_mt[m] = make_float4(tx, ty, tw, th);
    }
}

// ---------------- K2: fused reduction over the unified work index ----------------
__global__ void k_main(const float* __restrict__ in)
{
    const int S1 = NCELL;            // [0,S1)       conf over all cells (t=0)
    const int S2 = S1 + NT;          // [S1,S2)      masked x/y/w/h/conf
    const int S3 = S2 + NT * Cn;     // [S2,S3)      masked class base terms (t=0)
    const int S4 = S3 + NT;          // [S3,S4)      class one-hot corrections
    const int S5 = S4 + NT * An;     // [S4,S5)      noobj-zeroed conf terms

    int nlist = g_nlist, npair = g_npair, nzero = g_nzero;

    double acc[8];
#pragma unroll
    for (int i = 0; i < 8; i++) acc[i] = 0.0;

    int stride = gridDim.x * blockDim.x;
    for (int i = blockIdx.x * blockDim.x + threadIdx.x; i < S5; i += stride) {
        if (i < S1) {
            int b = i / AHW, r = i - b * AHW;
            int a = r / HW,  hw = r - a * HW;
            float l = in[(size_t)(b * NCH + a * CH + 4) * HW + hw];
            acc[5] += (double)(-clog(1.0f - sigf(l)));
        } else if (i < S2) {
            int k = i - S1;
            if (k < nlist) {
                int cell = g_mcell[k]; float4 tv = g_mt[k];
                int b = cell / AHW, r = cell - b * AHW;
                int a = r / HW,    hw = r - a * HW;
                const float* base = in + (size_t)(b * NCH + a * CH) * HW + hw;
                float xl = base[0], yl = base[HW], wl = base[2 * HW];
                float hl = base[3 * HW], cl = base[4 * HW];
                float px = sigf(xl), py = sigf(yl), pc = sigf(cl);
                acc[0] += (double)(-(tv.x * clog(px) + (1.0f - tv.x) * clog(1.0f - px)));
                acc[1] += (double)(-(tv.y * clog(py) + (1.0f - tv.y) * clog(1.0f - py)));
                float dw = wl - tv.z, dh = hl - tv.w;
                acc[2] += (double)(dw * dw);
                acc[3] += (double)(dh * dh);
                acc[4] += (double)(-clog(pc));
            }
        } else if (i < S3) {
            int idx = i - S2;
            int k = idx / Cn, cc = idx - k * Cn;
            if (k < nlist) {
                int cell = g_mcell[k];
                int b = cell / AHW, r = cell - b * AHW;
                int a = r / HW,    hw = r - a * HW;
                float l = in[(size_t)(b * NCH + a * CH + 5 + cc) * HW + hw];
                acc[7] += (double)(-clog(1.0f - sigf(l)));
            }
        } else if (i < S4) {
            int j = i - S3;
            if (j < npair) {
                int key = g_pair[j];
                int cell = key / Cn, cc = key - cell * Cn;
                int b = cell / AHW, r = cell - b * AHW;
                int a = r / HW,    hw = r - a * HW;
                float l = in[(size_t)(b * NCH + a * CH + 5 + cc) * HW + hw];
                float p = sigf(l);
                acc[7] += (double)(clog(1.0f - p) - clog(p)); // bce(p,1)-bce(p,0)
            }
        } else {
            int j = i - S4;
            if (j < nzero) {
                int cell = g_zcell[j];
                int b = cell / AHW, r = cell - b * AHW;
                int a = r / HW,    hw = r - a * HW;
                float l = in[(size_t)(b * NCH + a * CH + 4) * HW + hw];
                acc[6] += (double)(-clog(1.0f - sigf(l)));
            }
        }
    }

    // warp reduce (8 fp64 lanes worth)
#pragma unroll
    for (int off = 16; off; off >>= 1)
#pragma unroll
        for (int i = 0; i < 8; i++)
            acc[i] += __shfl_down_sync(0xffffffffu, acc[i], off);

    __shared__ double sred[8][8];    // [warp][acc], blockDim = 256 -> 8 warps
    int warp = threadIdx.x >> 5, lane = threadIdx.x & 31;
    if (lane == 0)
#pragma unroll
        for (int i = 0; i < 8; i++) sred[warp][i] = acc[i];
    __syncthreads();
    if (threadIdx.x < 8) {
        double s = 0.0;
        int nw = blockDim.x >> 5;
        for (int wg = 0; wg < nw; wg++) s += sred[wg][threadIdx.x];
        atomicAdd(&g_acc[threadIdx.x], s);
    }
}

// ---------------- K3: finalize 7 scalars ----------------
__global__ void k_final(float* __restrict__ out)
{
    float nm  = (float)g_nlist;
    float nnm = (float)(NCELL - g_nzero);
    const float inv = 1.0f / (float)NCELL;
    float lx = ((float)g_acc[0] * inv) / nm;
    float ly = ((float)g_acc[1] * inv) / nm;
    float lw = ((float)g_acc[2] * inv) / nm;
    float lh = ((float)g_acc[3] * inv) / nm;
    float lconf = ((float)g_acc[4] * inv) / nm
                + 0.5f * ((float)(g_acc[5] - g_acc[6]) * inv) / nnm;
    float lcls = ((float)g_acc[7] / (nm * (float)Cn)) / nm;
    float loss = 2.5f * (lx + ly) + 2.5f * (lw + lh) + lconf + lcls;
    out[0] = loss; out[1] = lx; out[2] = ly; out[3] = lw;
    out[4] = lh;   out[5] = lconf; out[6] = lcls;
}

// ---------------- launch ----------------
extern "C" void kernel_launch(void* const* d_in, const int* in_sizes, int n_in,
                              void* d_out, int out_size)
{
    const float* in  = (const float*)d_in[0];   // (16, 255, 76, 76) fp32
    const float* tgt = (const float*)d_in[1];   // (16, 50, 5) fp32
    float* out = (float*)d_out;                 // 7 fp32 scalars

    k_targets<<<1, NT>>>(tgt);
    k_main<<<296, 256>>>(in);
    k_final<<<1, 1>>>(out);
}

// round 9
// speedup vs baseline: 1.0952x; 1.0952x over previous
#include <cuda_runtime.h>

// ---------------- problem constants ----------------
#define Bn 16
#define An 3
#define Cn 80
#define Hn 76
#define Wn 76
#define Tn 50
#define HW (Hn * Wn)          // 5776
#define AHW (An * HW)         // 17328
#define NCELL (Bn * AHW)      // 277248
#define NT (Bn * Tn)          // 800
#define CH (5 + Cn)           // 85
#define NCH (An * CH)         // 255

// ---------------- device scratch (static: no allocations; zero-init) ----------------
__device__ int    g_win[NCELL];        // winner tag per cell (self-cleaned per launch)
__device__ int    g_nlist, g_npair, g_nzero;   // reset by k_final each cycle
__device__ int    g_mcell[NT];
__device__ float4 g_mt[NT];            // tx, ty, tw, th (winner's values)
__device__ int    g_pair[NT];          // cell*Cn + cls
__device__ int    g_zcell[NT * An];    // noobj-zeroed cells
__device__ double g_acc[8];            // 0:x 1:y 2:w 3:h 4:conf_obj 5:conf_all 6:conf_zero 7:cls

// softplus(l) = -log(1 - sigmoid(l)) = log(1 + e^l); clip(-100) never active for |l|<17
__device__ __forceinline__ float spf(float l) {
    return 0.6931471805599453f * __log2f(1.0f + exp2f(l * 1.4426950408889634f));
}

// ---------------- K1: build targets (one block per batch, R5-verbatim math) ----------
__global__ void k_targets(const float* __restrict__ tgt)
{
    int b = blockIdx.x;                 // 0..15
    int t = threadIdx.x;                // 0..63, active t < Tn
    bool active = (t < Tn);
    int j = b * Tn + t;

    float c = 0.f, xx = 0.f, yy = 0.f, ww = 0.f, hh = 0.f;
    if (active) {
        const float* p = tgt + j * 5;
        c = p[0]; xx = p[1]; yy = p[2]; ww = p[3]; hh = p[4];
    }
    bool valid = active && ((c + xx + yy + ww + hh) != 0.0f);

    float gx = xx * (float)Wn, gy = yy * (float)Hn;
    float gw = ww * (float)Wn, gh = hh * (float)Hn;
    int gi = (int)gx, gj = (int)gy;

    const float aw0 = 1.25f,  aw1 = 2.0f,  aw2 = 4.125f;
    const float ah0 = 1.625f, ah1 = 3.75f, ah2 = 2.875f;
    const float a20 = 5.90625f, a21 = 14.25f, a22 = 19.859375f;

    float a1 = (gw + 1.0f) * (gh + 1.0f);
    float i0 = fmaxf(fminf(gw, aw0) + 1.0f, 0.0f) * fmaxf(fminf(gh, ah0) + 1.0f, 0.0f);
    float i1 = fmaxf(fminf(gw, aw1) + 1.0f, 0.0f) * fmaxf(fminf(gh, ah1) + 1.0f, 0.0f);
    float i2 = fmaxf(fminf(gw, aw2) + 1.0f, 0.0f) * fmaxf(fminf(gh, ah2) + 1.0f, 0.0f);
    float u0 = i0 / (a1 + a20 - i0 + 1e-16f);
    float u1 = i1 / (a1 + a21 - i1 + 1e-16f);
    float u2 = i2 / (a1 + a22 - i2 + 1e-16f);

    int best = 0; float bi = u0;
    if (u1 > bi) { best = 1; bi = u1; }
    if (u2 > bi) { best = 2; bi = u2; }

    bool ok = valid && (gj < Hn) && (gi < Wn) && (gj >= 0) && (gi >= 0);
    int cell = ((b * An + best) * Hn + gj) * Wn + gi;

    // clear winner slots for cells this block will contest (batch-disjoint regions)
    if (ok) g_win[cell] = 0;
    __syncthreads();

    // last-writer-wins election (bit-identical to R5)
    if (ok) atomicMax(&g_win[cell], t + 1);

    if (valid) {
        if (u0 > 0.5f) { int z = ((b * An + 0) * Hn + gj) * Wn + gi;
                         if (z >= 0 && z < NCELL) g_zcell[atomicAdd(&g_nzero, 1)] = z; }
        if (u1 > 0.5f) { int z = ((b * An + 1) * Hn + gj) * Wn + gi;
                         if (z >= 0 && z < NCELL) g_zcell[atomicAdd(&g_nzero, 1)] = z; }
        if (u2 > 0.5f) { int z = ((b * An + 2) * Hn + gj) * Wn + gi;
                         if (z >= 0 && z < NCELL) g_zcell[atomicAdd(&g_nzero, 1)] = z; }
    }
    if (ok) g_pair[atomicAdd(&g_npair, 1)] = cell * Cn + (int)c;

    __syncthreads();

    if (ok && g_win[cell] == t + 1) {
        float tx = gx - (float)gi;
        float ty = gy - (float)gj;
        float awb = (best == 0) ? aw0 : (best == 1 ? aw1 : aw2);
        float ahb = (best == 0) ? ah0 : (best == 1 ? ah1 : ah2);
        float tw = logf(gw / awb + 1e-16f);
        float th = logf(gh / ahb + 1e-16f);
        int m = atomicAdd(&g_nlist, 1);
        g_mcell[m] = cell;
        g_mt[m] = make_float4(tx, ty, tw, th);
    }
}

// ---------------- K2: fused reduction (R5 structure, softplus + float4) -------------
__global__ void k_main(const float* __restrict__ in)
{
    const int N0 = NCELL / 4;        // float4 conf terms
    const int S2 = N0 + NT;          // masked x/y/w/h/conf
    const int S3 = S2 + NT * Cn;     // class base terms
    const int S4 = S3 + NT;          // pair corrections (exact -logit)
    const int S5 = S4 + NT * An;     // noobj-zeroed conf terms

    int nlist = g_nlist, npair = g_npair, nzero = g_nzero;

    double acc[8];
#pragma unroll
    for (int i = 0; i < 8; i++) acc[i] = 0.0;

    int stride = gridDim.x * blockDim.x;
    for (int i = blockIdx.x * blockDim.x + threadIdx.x; i < S5; i += stride) {
        if (i < N0) {
            int c4 = i * 4;
            int b = c4 / AHW, r = c4 - b * AHW;
            int a = r / HW,   hw = r - a * HW;
            const float4 v = *(const float4*)(in + (size_t)(b * NCH + a * CH + 4) * HW + hw);
            acc[5] += (double)spf(v.x);
            acc[5] += (double)spf(v.y);
            acc[5] += (double)spf(v.z);
            acc[5] += (double)spf(v.w);
        } else if (i < S2) {
            int k = i - N0;
            if (k < nlist) {
                int cell = g_mcell[k]; float4 tv = g_mt[k];
                int b = cell / AHW, r = cell - b * AHW;
                int a = r / HW,    hw = r - a * HW;
                const float* base = in + (size_t)(b * NCH + a * CH) * HW + hw;
                float xl = base[0], yl = base[HW], wl = base[2 * HW];
                float hl = base[3 * HW], cl = base[4 * HW];
                // bce(sig(l), t) = t*sp(-l) + (1-t)*sp(l)
                acc[0] += (double)(tv.x * spf(-xl) + (1.0f - tv.x) * spf(xl));
                acc[1] += (double)(tv.y * spf(-yl) + (1.0f - tv.y) * spf(yl));
                float dw = wl - tv.z, dh = hl - tv.w;
                acc[2] += (double)(dw * dw);
                acc[3] += (double)(dh * dh);
                acc[4] += (double)spf(-cl);              // bce(conf,1)
            }
        } else if (i < S3) {
            int idx = i - S2;
            int k = idx / Cn, cc = idx - k * Cn;
            if (k < nlist) {
                int cell = g_mcell[k];
                int b = cell / AHW, r = cell - b * AHW;
                int a = r / HW,    hw = r - a * HW;
                float l = in[(size_t)(b * NCH + a * CH + 5 + cc) * HW + hw];
                acc[7] += (double)spf(l);                // bce(pcls,0)
            }
        } else if (i < S4) {
            int jI = i - S3;
            if (jI < npair) {
                int key = g_pair[jI];
                int cell = key / Cn, cc = key - cell * Cn;
                int b = cell / AHW, r = cell - b * AHW;
                int a = r / HW,    hw = r - a * HW;
                float l = in[(size_t)(b * NCH + a * CH + 5 + cc) * HW + hw];
                acc[7] += (double)(-l);                  // bce(p,1)-bce(p,0) = -logit (exact)
            }
        } else {
            int jI = i - S4;
            if (jI < nzero) {
                int cell = g_zcell[jI];
                int b = cell / AHW, r = cell - b * AHW;
                int a = r / HW,    hw = r - a * HW;
                float l = in[(size_t)(b * NCH + a * CH + 4) * HW + hw];
                acc[6] += (double)spf(l);                // subtract noobj-zeroed conf term
            }
        }
    }

    // warp reduce -> smem -> 8 global fp64 atomics (R5-identical)
#pragma unroll
    for (int off = 16; off; off >>= 1)
#pragma unroll
        for (int i = 0; i < 8; i++)
            acc[i] += __shfl_down_sync(0xffffffffu, acc[i], off);

    __shared__ double sred[8][8];
    int warp = threadIdx.x >> 5, lane = threadIdx.x & 31;
    if (lane == 0)
#pragma unroll
        for (int i = 0; i < 8; i++) sred[warp][i] = acc[i];
    __syncthreads();
    if (threadIdx.x < 8) {
        double s = 0.0;
        int nw = blockDim.x >> 5;
        for (int wg = 0; wg < nw; wg++) s += sred[wg][threadIdx.x];
        atomicAdd(&g_acc[threadIdx.x], s);
    }
}

// ---------------- K3: finalize + state reset for next replay ------------------------
__global__ void k_final(float* __restrict__ out)
{
    float nm  = (float)g_nlist;
    float nnm = (float)(NCELL - g_nzero);
    const float inv = 1.0f / (float)NCELL;
    float lx = ((float)g_acc[0] * inv) / nm;
    float ly = ((float)g_acc[1] * inv) / nm;
    float lw = ((float)g_acc[2] * inv) / nm;
    float lh = ((float)g_acc[3] * inv) / nm;
    float lconf = ((float)g_acc[4] * inv) / nm
                + 0.5f * ((float)(g_acc[5] - g_acc[6]) * inv) / nnm;
    float lcls = ((float)g_acc[7] / (nm * (float)Cn)) / nm;
    float loss = 2.5f * (lx + ly) + 2.5f * (lw + lh) + lconf + lcls;
    out[0] = loss; out[1] = lx; out[2] = ly; out[3] = lw;
    out[4] = lh;   out[5] = lconf; out[6] = lcls;
    // reset all cross-launch state (kernel-boundary ordered; statics zero-init first call)
#pragma unroll
    for (int i = 0; i < 8; i++) g_acc[i] = 0.0;
    g_nlist = 0; g_npair = 0; g_nzero = 0;
}

// ---------------- launch ----------------
extern "C" void kernel_launch(void* const* d_in, const int* in_sizes, int n_in,
                              void* d_out, int out_size)
{
    const float* in  = (const float*)d_in[0];   // (16, 255, 76, 76) fp32
    const float* tgt = (const float*)d_in[1];   // (16, 50, 5) fp32
    float* out = (float*)d_out;                 // 7 fp32 scalars

    k_targets<<<Bn, 64>>>(tgt);
    k_main<<<296, 256>>>(in);
    k_final<<<1, 1>>>(out);
}